// round 2
// baseline (speedup 1.0000x reference)
#include <cuda_runtime.h>

// Problem constants (fixed shapes from reference setup_inputs)
#define B_   16
#define J_   1024
#define L_   4096
#define D_   512
#define D4   128          // D/4 float4 lanes
#define NCH  16           // chunks along J
#define CLEN 64           // J per chunk
#define EPSV 1e-4f

// Scratch (device globals — no allocation allowed in kernel_launch)
__device__ float  g_partialA[B_ * NCH];            // per-chunk decay product
__device__ float4 g_partialEnd[B_ * NCH * D4];     // per-chunk end state (prev=0 start)
__device__ float4 g_carry[B_ * NCH * D4];          // state entering each chunk
__device__ float4 g_smoothed[B_ * J_ * D4];        // 32 MiB intermediate
__device__ int    g_idx[B_ * L_];                  // gather indices

// ---------------------------------------------------------------------------
// Kernel 1: per-chunk partial EMA from prev=0; record end state + prod(a)
// grid (NCH, B), 128 threads (one float4 lane each)
// ---------------------------------------------------------------------------
__global__ void k_partial(const float4* __restrict__ emb,
                          const float*  __restrict__ conf,
                          const int*    __restrict__ mask) {
    const int c = blockIdx.x, b = blockIdx.y, t = threadIdx.x;
    __shared__ float sa[CLEN], sb[CLEN];
    if (t < CLEN) {
        const int j = c * CLEN + t;
        float p = conf[b * J_ + j];
        p = fminf(fmaxf(p, EPSV), 1.0f - EPSV);
        const bool m = mask[b * J_ + j] != 0;
        sa[t] = m ? (1.0f - p) : 1.0f;
        sb[t] = m ? p : 0.0f;
    }
    __syncthreads();

    float4 prev = make_float4(0.f, 0.f, 0.f, 0.f);
    float  A = 1.0f;
    const float4* ep = emb + ((size_t)b * J_ + (size_t)c * CLEN) * D4 + t;
    #pragma unroll 8
    for (int jj = 0; jj < CLEN; jj++) {
        const float4 e = ep[(size_t)jj * D4];
        const float a = sa[jj], bb = sb[jj];
        prev.x = fmaf(a, prev.x, bb * e.x);
        prev.y = fmaf(a, prev.y, bb * e.y);
        prev.z = fmaf(a, prev.z, bb * e.z);
        prev.w = fmaf(a, prev.w, bb * e.w);
        A *= a;
    }
    g_partialEnd[(b * NCH + c) * D4 + t] = prev;
    if (t == 0) g_partialA[b * NCH + c] = A;
}

// ---------------------------------------------------------------------------
// Kernel 2: sequential combine of 16 chunk carries per (b, d4)
// grid (B), 128 threads
// ---------------------------------------------------------------------------
__global__ void k_carry() {
    const int b = blockIdx.x, t = threadIdx.x;
    __shared__ float sA[NCH];
    if (t < NCH) sA[t] = g_partialA[b * NCH + t];
    __syncthreads();

    float4 s = make_float4(0.f, 0.f, 0.f, 0.f);
    g_carry[(b * NCH + 0) * D4 + t] = s;
    #pragma unroll
    for (int c = 1; c < NCH; c++) {
        const float4 e = g_partialEnd[(b * NCH + c - 1) * D4 + t];
        const float A = sA[c - 1];
        s.x = fmaf(A, s.x, e.x);
        s.y = fmaf(A, s.y, e.y);
        s.z = fmaf(A, s.z, e.z);
        s.w = fmaf(A, s.w, e.w);
        g_carry[(b * NCH + c) * D4 + t] = s;
    }
}

// ---------------------------------------------------------------------------
// Kernel 3: replay each chunk from its carry; write smoothed
// grid (NCH, B), 128 threads
// ---------------------------------------------------------------------------
__global__ void k_final(const float4* __restrict__ emb,
                        const float*  __restrict__ conf,
                        const int*    __restrict__ mask) {
    const int c = blockIdx.x, b = blockIdx.y, t = threadIdx.x;
    __shared__ float sa[CLEN], sb[CLEN];
    if (t < CLEN) {
        const int j = c * CLEN + t;
        float p = conf[b * J_ + j];
        p = fminf(fmaxf(p, EPSV), 1.0f - EPSV);
        const bool m = mask[b * J_ + j] != 0;
        sa[t] = m ? (1.0f - p) : 1.0f;
        sb[t] = m ? p : 0.0f;
    }
    __syncthreads();

    float4 prev = g_carry[(b * NCH + c) * D4 + t];
    const float4* ep = emb + ((size_t)b * J_ + (size_t)c * CLEN) * D4 + t;
    float4* sp = g_smoothed + ((size_t)b * J_ + (size_t)c * CLEN) * D4 + t;
    #pragma unroll 8
    for (int jj = 0; jj < CLEN; jj++) {
        const float4 e = ep[(size_t)jj * D4];
        const float a = sa[jj], bb = sb[jj];
        prev.x = fmaf(a, prev.x, bb * e.x);
        prev.y = fmaf(a, prev.y, bb * e.y);
        prev.z = fmaf(a, prev.z, bb * e.z);
        prev.w = fmaf(a, prev.w, bb * e.w);
        sp[(size_t)jj * D4] = prev;
    }
}

// ---------------------------------------------------------------------------
// Kernel 4: per-batch inclusive scan of boundary_mask (int32) -> gather idx
// grid (B), 256 threads, 16 elems/thread
// ---------------------------------------------------------------------------
__global__ void k_idx(const int* __restrict__ bnd) {
    const int b = blockIdx.x, t = threadIdx.x;
    __shared__ int ssum[256];
    const int* p = bnd + b * L_ + t * 16;
    int v[16];
    int s = 0;
    #pragma unroll
    for (int i = 0; i < 16; i++) { v[i] = p[i]; s += (v[i] != 0); }
    ssum[t] = s;
    __syncthreads();
    // Hillis-Steele inclusive scan over 256 thread sums
    for (int off = 1; off < 256; off <<= 1) {
        int val = (t >= off) ? ssum[t - off] : 0;
        __syncthreads();
        ssum[t] += val;
        __syncthreads();
    }
    int run = ssum[t] - s;   // exclusive prefix
    int* op = g_idx + b * L_ + t * 16;
    #pragma unroll
    for (int i = 0; i < 16; i++) {
        run += (v[i] != 0);
        int id = run - 1;
        id = id < 0 ? 0 : (id > (J_ - 1) ? (J_ - 1) : id);
        op[i] = id;
    }
}

// ---------------------------------------------------------------------------
// Kernel 5: gather/upsample. out[b,l,:] = smoothed[b, idx[b,l], :]
// linear tid == output float4 index; idx load broadcasts across 128 threads
// ---------------------------------------------------------------------------
__global__ void k_gather(float4* __restrict__ out) {
    const unsigned int tid = blockIdx.x * blockDim.x + threadIdx.x;
    const int d = tid & (D4 - 1);
    const int l = (tid >> 7) & (L_ - 1);
    const int b = tid >> 19;
    const int j = g_idx[b * L_ + l];
    out[tid] = g_smoothed[((size_t)b * J_ + j) * D4 + d];
}

// ---------------------------------------------------------------------------
extern "C" void kernel_launch(void* const* d_in, const int* in_sizes, int n_in,
                              void* d_out, int out_size) {
    const float4* emb  = (const float4*)d_in[0];  // (16,1024,512) f32
    const float*  conf = (const float*)d_in[1];   // (16,1024) f32
    const int*    msk  = (const int*)d_in[2];     // (16,1024) bool -> int32
    const int*    bnd  = (const int*)d_in[3];     // (16,4096) bool -> int32
    float4* out = (float4*)d_out;                 // (16,4096,512) f32

    k_partial<<<dim3(NCH, B_), D4>>>(emb, conf, msk);
    k_carry<<<B_, D4>>>();
    k_final<<<dim3(NCH, B_), D4>>>(emb, conf, msk);
    k_idx<<<B_, 256>>>(bnd);
    const int total4 = B_ * L_ * D4;              // 8,388,608
    k_gather<<<total4 / 256, 256>>>(out);
}

// round 3
// speedup vs baseline: 1.1975x; 1.1975x over previous
#include <cuda_runtime.h>

// Fixed shapes
#define B_   16
#define J_   1024
#define L_   4096
#define D_   512
#define D4   128          // D/4 float4 lanes
#define NCH  32           // chunks along J
#define CLEN 32           // J per chunk (== warp size)
#define EPSV 1e-4f

// Scratch (device globals)
__device__ float  g_partialA[B_ * NCH];          // per-chunk total decay product
__device__ float  g_cumA[B_ * J_];               // within-chunk inclusive prod(a)
__device__ float4 g_partialEnd[B_ * NCH * D4];   // per-chunk end state (prev=0)
__device__ float4 g_carry[B_ * NCH * D4];        // state entering each chunk
__device__ float4 g_smoothed[B_ * J_ * D4];      // prev=0 partial scan, 32 MiB
__device__ int    g_idx[B_ * L_];                // gather indices

// ---------------------------------------------------------------------------
// Kernel 1: per-chunk partial EMA from prev=0 (written to g_smoothed),
// plus within-chunk cumulative decay cumA and chunk end state / total A.
// grid (NCH, B), 128 threads (one float4 lane each)
// ---------------------------------------------------------------------------
__global__ void k_partial(const float4* __restrict__ emb,
                          const float*  __restrict__ conf,
                          const int*    __restrict__ mask) {
    const int c = blockIdx.x, b = blockIdx.y, t = threadIdx.x;
    __shared__ float sa[CLEN], sb[CLEN];

    if (t < CLEN) {  // warp 0 exactly
        const int j = c * CLEN + t;
        float p = conf[b * J_ + j];
        p = fminf(fmaxf(p, EPSV), 1.0f - EPSV);
        const bool m = mask[b * J_ + j] != 0;
        const float a = m ? (1.0f - p) : 1.0f;
        sa[t] = a;
        sb[t] = m ? p : 0.0f;
        // warp-inclusive product scan of a
        float prod = a;
        #pragma unroll
        for (int off = 1; off < 32; off <<= 1) {
            float v = __shfl_up_sync(0xFFFFFFFFu, prod, off);
            if (t >= off) prod *= v;
        }
        g_cumA[b * J_ + j] = prod;
        if (t == CLEN - 1) g_partialA[b * NCH + c] = prod;
    }
    __syncthreads();

    float4 prev = make_float4(0.f, 0.f, 0.f, 0.f);
    const size_t base = ((size_t)b * J_ + (size_t)c * CLEN) * D4 + t;
    const float4* ep = emb + base;
    float4* sp = g_smoothed + base;
    #pragma unroll 8
    for (int jj = 0; jj < CLEN; jj++) {
        const float4 e = ep[(size_t)jj * D4];
        const float a = sa[jj], bb = sb[jj];
        prev.x = fmaf(a, prev.x, bb * e.x);
        prev.y = fmaf(a, prev.y, bb * e.y);
        prev.z = fmaf(a, prev.z, bb * e.z);
        prev.w = fmaf(a, prev.w, bb * e.w);
        sp[(size_t)jj * D4] = prev;
    }
    g_partialEnd[(b * NCH + c) * D4 + t] = prev;
}

// ---------------------------------------------------------------------------
// Kernel 2: combine chunk carries per (b, d4). Preload all ends (MLP=NCH),
// then the NCH-step serial combine runs register-resident.
// grid (B), 128 threads
// ---------------------------------------------------------------------------
__global__ void k_carry() {
    const int b = blockIdx.x, t = threadIdx.x;
    __shared__ float sA[NCH];
    if (t < NCH) sA[t] = g_partialA[b * NCH + t];

    float4 e[NCH];
    #pragma unroll
    for (int c = 0; c < NCH; c++)
        e[c] = g_partialEnd[(b * NCH + c) * D4 + t];
    __syncthreads();

    float4 s = make_float4(0.f, 0.f, 0.f, 0.f);
    g_carry[(b * NCH + 0) * D4 + t] = s;
    #pragma unroll
    for (int c = 1; c < NCH; c++) {
        const float A = sA[c - 1];
        s.x = fmaf(A, s.x, e[c - 1].x);
        s.y = fmaf(A, s.y, e[c - 1].y);
        s.z = fmaf(A, s.z, e[c - 1].z);
        s.w = fmaf(A, s.w, e[c - 1].w);
        g_carry[(b * NCH + c) * D4 + t] = s;
    }
}

// ---------------------------------------------------------------------------
// Kernel 3: per-batch inclusive scan of boundary_mask (int32) -> gather idx
// grid (B), 256 threads, 16 elems/thread; warp-shuffle scan (2 barriers)
// ---------------------------------------------------------------------------
__global__ void k_idx(const int* __restrict__ bnd) {
    const int b = blockIdx.x, t = threadIdx.x;
    const int lane = t & 31, w = t >> 5;   // 8 warps
    __shared__ int wsum[8];

    const int* p = bnd + b * L_ + t * 16;
    int v[16];
    int s = 0;
    #pragma unroll
    for (int i = 0; i < 16; i++) { v[i] = p[i]; s += (v[i] != 0); }

    // warp-inclusive scan of per-thread sums
    int incl = s;
    #pragma unroll
    for (int off = 1; off < 32; off <<= 1) {
        int u = __shfl_up_sync(0xFFFFFFFFu, incl, off);
        if (lane >= off) incl += u;
    }
    if (lane == 31) wsum[w] = incl;
    __syncthreads();
    if (t < 8) {
        int x = wsum[t];
        #pragma unroll
        for (int off = 1; off < 8; off <<= 1) {
            int u = __shfl_up_sync(0x000000FFu, x, off);
            if (t >= off) x += u;
        }
        wsum[t] = x;
    }
    __syncthreads();

    int run = incl - s + (w ? wsum[w - 1] : 0);   // exclusive prefix
    int* op = g_idx + b * L_ + t * 16;
    #pragma unroll
    for (int i = 0; i < 16; i++) {
        run += (v[i] != 0);
        int id = run - 1;
        id = id < 0 ? 0 : (id > (J_ - 1) ? (J_ - 1) : id);
        op[i] = id;
    }
}

// ---------------------------------------------------------------------------
// Kernel 4: fused correction + gather.
// out[b,l,d] = partial[b,j,d] + cumA[b,j] * carry[b, j/CLEN, d],  j = idx[b,l]
// ---------------------------------------------------------------------------
__global__ void k_gather(float4* __restrict__ out) {
    const unsigned int tid = blockIdx.x * blockDim.x + threadIdx.x;
    const int d = tid & (D4 - 1);
    const int l = (tid >> 7) & (L_ - 1);
    const int b = tid >> 19;

    const int j = g_idx[b * L_ + l];
    const float w = g_cumA[b * J_ + j];
    const int c = j / CLEN;
    const float4 pv = g_smoothed[((size_t)b * J_ + j) * D4 + d];
    const float4 cv = g_carry[(b * NCH + c) * D4 + d];
    float4 r;
    r.x = fmaf(w, cv.x, pv.x);
    r.y = fmaf(w, cv.y, pv.y);
    r.z = fmaf(w, cv.z, pv.z);
    r.w = fmaf(w, cv.w, pv.w);
    out[tid] = r;
}

// ---------------------------------------------------------------------------
extern "C" void kernel_launch(void* const* d_in, const int* in_sizes, int n_in,
                              void* d_out, int out_size) {
    const float4* emb  = (const float4*)d_in[0];  // (16,1024,512) f32
    const float*  conf = (const float*)d_in[1];   // (16,1024) f32
    const int*    msk  = (const int*)d_in[2];     // (16,1024) bool->int32
    const int*    bnd  = (const int*)d_in[3];     // (16,4096) bool->int32
    float4* out = (float4*)d_out;                 // (16,4096,512) f32

    k_partial<<<dim3(NCH, B_), D4>>>(emb, conf, msk);
    k_carry<<<B_, D4>>>();
    k_idx<<<B_, 256>>>(bnd);
    const int total4 = B_ * L_ * D4;              // 8,388,608
    k_gather<<<total4 / 256, 256>>>(out);
}

// round 4
// speedup vs baseline: 1.4344x; 1.1978x over previous
#include <cuda_runtime.h>

// Fixed shapes
#define B_   16
#define J_   1024
#define L_   4096
#define D_   512
#define D4   128          // D/4 float4 lanes
#define NCH  32           // chunks along J
#define CLEN 32           // J per chunk (== warp size)
#define EPSV 1e-4f

// Scratch (device globals)
__device__ float  g_partialA[B_ * NCH];          // per-chunk total decay product
__device__ float  g_cumA[B_ * J_];               // within-chunk inclusive prod(a)
__device__ float4 g_partialEnd[B_ * NCH * D4];   // per-chunk end state (prev=0)
__device__ float4 g_carry[B_ * NCH * D4];        // state entering each chunk
__device__ float4 g_smoothed[B_ * J_ * D4];      // prev=0 partial scan, 32 MiB
__device__ int    g_idx[B_ * L_];                // gather indices

// ---------------------------------------------------------------------------
// Kernel 1: per-chunk partial EMA from prev=0 (written to g_smoothed),
// plus within-chunk cumulative decay cumA and chunk end state / total A.
// grid (NCH, B), 128 threads (one float4 lane each)
// ---------------------------------------------------------------------------
__global__ void k_partial(const float4* __restrict__ emb,
                          const float*  __restrict__ conf,
                          const int*    __restrict__ mask) {
    const int c = blockIdx.x, b = blockIdx.y, t = threadIdx.x;
    __shared__ float sa[CLEN], sb[CLEN];

    if (t < CLEN) {  // warp 0 exactly
        const int j = c * CLEN + t;
        float p = conf[b * J_ + j];
        p = fminf(fmaxf(p, EPSV), 1.0f - EPSV);
        const bool m = mask[b * J_ + j] != 0;
        const float a = m ? (1.0f - p) : 1.0f;
        sa[t] = a;
        sb[t] = m ? p : 0.0f;
        // warp-inclusive product scan of a
        float prod = a;
        #pragma unroll
        for (int off = 1; off < 32; off <<= 1) {
            float v = __shfl_up_sync(0xFFFFFFFFu, prod, off);
            if (t >= off) prod *= v;
        }
        g_cumA[b * J_ + j] = prod;
        if (t == CLEN - 1) g_partialA[b * NCH + c] = prod;
    }
    __syncthreads();

    float4 prev = make_float4(0.f, 0.f, 0.f, 0.f);
    const size_t base = ((size_t)b * J_ + (size_t)c * CLEN) * D4 + t;
    const float4* ep = emb + base;
    float4* sp = g_smoothed + base;
    #pragma unroll 8
    for (int jj = 0; jj < CLEN; jj++) {
        const float4 e = ep[(size_t)jj * D4];
        const float a = sa[jj], bb = sb[jj];
        prev.x = fmaf(a, prev.x, bb * e.x);
        prev.y = fmaf(a, prev.y, bb * e.y);
        prev.z = fmaf(a, prev.z, bb * e.z);
        prev.w = fmaf(a, prev.w, bb * e.w);
        sp[(size_t)jj * D4] = prev;
    }
    g_partialEnd[(b * NCH + c) * D4 + t] = prev;
}

// ---------------------------------------------------------------------------
// Kernel 2 (merged): blocks 0..15 -> carry combine; blocks 16..31 -> idx scan
// ---------------------------------------------------------------------------
__global__ void k_mid(const int* __restrict__ bnd) {
    if (blockIdx.x < B_) {
        // ---- carry combine: grid-slot b, 128 threads ----
        const int b = blockIdx.x, t = threadIdx.x;
        if (t >= D4) return;
        __shared__ float sA[NCH];
        if (t < NCH) sA[t] = g_partialA[b * NCH + t];

        float4 e[NCH];
        #pragma unroll
        for (int c = 0; c < NCH; c++)
            e[c] = g_partialEnd[(b * NCH + c) * D4 + t];
        __syncthreads();

        float4 s = make_float4(0.f, 0.f, 0.f, 0.f);
        g_carry[(b * NCH + 0) * D4 + t] = s;
        #pragma unroll
        for (int c = 1; c < NCH; c++) {
            const float A = sA[c - 1];
            s.x = fmaf(A, s.x, e[c - 1].x);
            s.y = fmaf(A, s.y, e[c - 1].y);
            s.z = fmaf(A, s.z, e[c - 1].z);
            s.w = fmaf(A, s.w, e[c - 1].w);
            g_carry[(b * NCH + c) * D4 + t] = s;
        }
    } else {
        // ---- boundary scan -> gather idx: 256 threads, 16 elems/thread ----
        const int b = blockIdx.x - B_, t = threadIdx.x;
        const int lane = t & 31, w = t >> 5;   // 8 warps
        __shared__ int wsum[8];

        const int* p = bnd + b * L_ + t * 16;
        int v[16];
        int s = 0;
        #pragma unroll
        for (int i = 0; i < 16; i++) { v[i] = p[i]; s += (v[i] != 0); }

        int incl = s;
        #pragma unroll
        for (int off = 1; off < 32; off <<= 1) {
            int u = __shfl_up_sync(0xFFFFFFFFu, incl, off);
            if (lane >= off) incl += u;
        }
        if (lane == 31) wsum[w] = incl;
        __syncthreads();
        if (t < 8) {
            int x = wsum[t];
            #pragma unroll
            for (int off = 1; off < 8; off <<= 1) {
                int u = __shfl_up_sync(0x000000FFu, x, off);
                if (t >= off) x += u;
            }
            wsum[t] = x;
        }
        __syncthreads();

        int run = incl - s + (w ? wsum[w - 1] : 0);   // exclusive prefix
        int* op = g_idx + b * L_ + t * 16;
        #pragma unroll
        for (int i = 0; i < 16; i++) {
            run += (v[i] != 0);
            int id = run - 1;
            id = id < 0 ? 0 : (id > (J_ - 1) ? (J_ - 1) : id);
            op[i] = id;
        }
    }
}

// ---------------------------------------------------------------------------
// Kernel 3: fused correction + gather, one warp per (b,l) row.
// out[b,l,d] = partial[b,j,d] + cumA[b,j] * carry[b, j>>5, d],  j = idx[b,l]
// Each lane handles 4 float4 (d = k*32 + lane) -> MLP 8, coalesced writes.
// ---------------------------------------------------------------------------
__global__ void k_gather(float4* __restrict__ out) {
    const unsigned int wg = (blockIdx.x * blockDim.x + threadIdx.x) >> 5;
    const int lane = threadIdx.x & 31;
    const int l = wg & (L_ - 1);
    const int b = wg >> 12;

    const int j = g_idx[b * L_ + l];
    const float w = g_cumA[b * J_ + j];
    const int c = j >> 5;
    const float4* __restrict__ sp = g_smoothed + ((size_t)b * J_ + j) * D4;
    const float4* __restrict__ cp = g_carry + (b * NCH + c) * D4;
    float4* __restrict__ op = out + ((size_t)b * L_ + l) * D4;

    float4 pv[4], cv[4];
    #pragma unroll
    for (int k = 0; k < 4; k++) {
        const int d = k * 32 + lane;
        pv[k] = sp[d];
        cv[k] = cp[d];
    }
    #pragma unroll
    for (int k = 0; k < 4; k++) {
        const int d = k * 32 + lane;
        float4 r;
        r.x = fmaf(w, cv[k].x, pv[k].x);
        r.y = fmaf(w, cv[k].y, pv[k].y);
        r.z = fmaf(w, cv[k].z, pv[k].z);
        r.w = fmaf(w, cv[k].w, pv[k].w);
        op[d] = r;
    }
}

// ---------------------------------------------------------------------------
extern "C" void kernel_launch(void* const* d_in, const int* in_sizes, int n_in,
                              void* d_out, int out_size) {
    const float4* emb  = (const float4*)d_in[0];  // (16,1024,512) f32
    const float*  conf = (const float*)d_in[1];   // (16,1024) f32
    const int*    msk  = (const int*)d_in[2];     // (16,1024) bool->int32
    const int*    bnd  = (const int*)d_in[3];     // (16,4096) bool->int32
    float4* out = (float4*)d_out;                 // (16,4096,512) f32

    k_partial<<<dim3(NCH, B_), D4>>>(emb, conf, msk);
    k_mid<<<2 * B_, 256>>>(bnd);
    // one warp per (b,l): 16*4096 warps = 2,097,152 threads
    k_gather<<<(B_ * L_ * 32) / 256, 256>>>(out);
}